// round 9
// baseline (speedup 1.0000x reference)
#include <cuda_runtime.h>
#include <cstdint>

#define N_SAMPLES 2048
#define N_CHAN    512
#define HW        49
#define N_GROUPS  64
#define CHB       8                       // channels per CTA
#define QCH       (N_CHAN / CHB)          // 64
#define NPAIR     (N_GROUPS * QCH)        // 4096 (g,q) pairs
#define SPLIT     2                       // sample-range halves
#define GRID      (NPAIR * SPLIT)         // 8192
#define HALF      (N_SAMPLES / SPLIT)     // 1024
#define THREADS   128
#define STRIP_F4  98                      // CHB*HW/4 float4 per member strip
#define SAMPLE_F4 (N_CHAN * HW / 4)       // 6272 float4 per sample

// Cross-CTA combine scratch (zero at module load; ticket self-resets each use).
__device__ float    g_part[GRID][CHB];    // per-(pair,half) channel sums
__device__ int      g_pcnt[GRID];         // per-(pair,half) member count
__device__ unsigned g_tick[NPAIR];        // arrival tickets

// One CTA per (group g, 8-channel chunk q, sample-half s). Scans its idx
// half, streams members' contiguous 1568-byte strips via LDG.128 into
// register accumulators (x4 member unroll for MLP), reduces to 8 channel
// sums, then pairwise-combines with its sibling CTA through a ticket.
// Output written exactly once; single launch; self-cleaning scratch.
__global__ __launch_bounds__(THREADS) void fused_kernel(
    const float* __restrict__ x,
    const int*   __restrict__ idx,
    float*       __restrict__ out)
{
    __shared__ unsigned short list[HALF];     // member sample ids
    __shared__ int            s_cnt;
    __shared__ float4         red4[STRIP_F4]; // 392 partials, 16B-aligned
    __shared__ int            s_second;

    const int pair = blockIdx.x & (NPAIR - 1);
    const int g    = pair & (N_GROUPS - 1);
    const int q    = pair >> 6;
    const int sh   = blockIdx.x >> 12;        // sample half 0/1
    const int tid  = threadIdx.x;
    const int slot = pair * SPLIT + sh;

    if (tid == 0) s_cnt = 0;
    __syncthreads();

    // ---- scan this CTA's idx half, compact members of group g ----
    const int4* __restrict__ idx4 = (const int4*)idx + sh * (HALF / 4);
    const int base = sh * HALF;
    for (int i = tid; i < HALF / 4; i += THREADS) {
        int4 v = idx4[i];
        int  b = base + 4 * i;
        if (v.x == g) list[atomicAdd(&s_cnt, 1)] = (unsigned short)(b + 0);
        if (v.y == g) list[atomicAdd(&s_cnt, 1)] = (unsigned short)(b + 1);
        if (v.z == g) list[atomicAdd(&s_cnt, 1)] = (unsigned short)(b + 2);
        if (v.w == g) list[atomicAdd(&s_cnt, 1)] = (unsigned short)(b + 3);
    }
    __syncthreads();
    const int cnt = s_cnt;

    const float4* __restrict__ xq = (const float4*)x + (size_t)q * STRIP_F4;
    const bool active = (tid < STRIP_F4);

    // ---- register-accumulating stream, unrolled x4 for MLP ----
    float4 acc = make_float4(0.f, 0.f, 0.f, 0.f);
    if (active) {
        int i = 0;
        for (; i + 4 <= cnt; i += 4) {
            const size_t o0 = (size_t)list[i + 0] * SAMPLE_F4;
            const size_t o1 = (size_t)list[i + 1] * SAMPLE_F4;
            const size_t o2 = (size_t)list[i + 2] * SAMPLE_F4;
            const size_t o3 = (size_t)list[i + 3] * SAMPLE_F4;
            float4 v0 = __ldg(xq + o0 + tid);
            float4 v1 = __ldg(xq + o1 + tid);
            float4 v2 = __ldg(xq + o2 + tid);
            float4 v3 = __ldg(xq + o3 + tid);
            acc.x += v0.x + v1.x + v2.x + v3.x;
            acc.y += v0.y + v1.y + v2.y + v3.y;
            acc.z += v0.z + v1.z + v2.z + v3.z;
            acc.w += v0.w + v1.w + v2.w + v3.w;
        }
        for (; i < cnt; i++) {
            float4 v = __ldg(xq + (size_t)list[i] * SAMPLE_F4 + tid);
            acc.x += v.x; acc.y += v.y; acc.z += v.z; acc.w += v.w;
        }
        red4[tid] = acc;
    }
    __syncthreads();

    // ---- reduce 392 partials -> 8 channel sums; publish partials ----
    float my_sum = 0.0f;
    if (tid < CHB) {
        const float* __restrict__ r = (const float*)red4 + tid * HW;
        #pragma unroll
        for (int e = 0; e < HW; e++) my_sum += r[e];
        g_part[slot][tid] = my_sum;
        if (tid == 0) g_pcnt[slot] = cnt;
        __threadfence();                   // writer-side fence, GPU scope
    }
    __syncthreads();

    if (tid == 0) {
        unsigned t = atomicAdd(&g_tick[pair], 1u);
        s_second = (t == 1u);
    }
    __syncthreads();
    if (!s_second) return;                 // first arriver exits

    // ---- combiner: read sibling partials from L2, finalize, reset ----
    const int oslot = pair * SPLIT + (1 - sh);
    if (tid < CHB) {
        float other = __ldcg(&g_part[oslot][tid]);
        int   ocnt  = __ldcg(&g_pcnt[oslot]);
        float total = my_sum + other;
        float rcp   = 1.0f / ((float)(cnt + ocnt) * (float)HW);
        out[g * N_CHAN + q * CHB + tid] = total * rcp;
    }
    if (tid == 0) g_tick[pair] = 0;        // self-clean for next replay
}

extern "C" void kernel_launch(void* const* d_in, const int* in_sizes, int n_in,
                              void* d_out, int out_size)
{
    const float* x   = (const float*)d_in[0];
    const int*   idx = (const int*)d_in[1];
    float*       out = (float*)d_out;

    (void)in_sizes; (void)n_in; (void)out_size;

    fused_kernel<<<GRID, THREADS>>>(x, idx, out);
}